// round 17
// baseline (speedup 1.0000x reference)
#include <cuda_runtime.h>
#include <cstdint>

#define B_ 256
#define T_ 2048
#define I_ 50
#define H_ 116
#define O_ 50
#define N_TOT (B_ * T_)

typedef unsigned long long u64;

// Device scratch (static allocation = allowed)
__device__ float g_xp[(size_t)N_TOT * H_];   // input projection [N, H]
__device__ float g_hs[(size_t)N_TOT * H_];   // hidden states    [N, H]
__device__ float g_dummy;

// ---------------- packed f32x2 helpers (Blackwell) ----------------
__device__ __forceinline__ u64 fma2(u64 a, u64 b, u64 c) {
    u64 d;
    asm("fma.rn.f32x2 %0, %1, %2, %3;" : "=l"(d) : "l"(a), "l"(b), "l"(c));
    return d;
}
__device__ __forceinline__ u64 add2(u64 a, u64 b) {
    u64 d;
    asm("add.rn.f32x2 %0, %1, %2;" : "=l"(d) : "l"(a), "l"(b));
    return d;
}
__device__ __forceinline__ float pair_sum(u64 a) {
    float lo = __uint_as_float((unsigned)(a & 0xFFFFFFFFull));
    float hi = __uint_as_float((unsigned)(a >> 32));
    return lo + hi;
}
__device__ __forceinline__ void cp16(void* smem, const void* gmem) {
    unsigned s = (unsigned)__cvta_generic_to_shared(smem);
    asm volatile("cp.async.ca.shared.global [%0], [%1], 16;" :: "r"(s), "l"(gmem));
}
__device__ __forceinline__ void cp8(void* smem, const void* gmem) {
    unsigned s = (unsigned)__cvta_generic_to_shared(smem);
    asm volatile("cp.async.ca.shared.global [%0], [%1], 8;" :: "r"(s), "l"(gmem));
}
#define CP_COMMIT() asm volatile("cp.async.commit_group;")
#define CP_WAIT(n)  asm volatile("cp.async.wait_group %0;" :: "n"(n))

// ================= xp GEMM: g_xp[n,j] = x[n,:]·W_ih[j,:] + b_ih[j]+b_hh[j] ==
#define XP_ROWS 32
#define XP_RPAD 52
#define XP_NT   (N_TOT / XP_ROWS)
__global__ void __launch_bounds__(256) xp_kernel(
    const float* __restrict__ x,
    const float* __restrict__ W_ih,
    const float* __restrict__ b_ih,
    const float* __restrict__ b_hh)
{
    __shared__ __align__(16) float xs[2][XP_ROWS * XP_RPAD];

    const int tid = threadIdx.x;
    const int j   = tid & 127;
    const int r2  = tid >> 7;
    const bool is_j = (j < H_);

    u64 wih[25];
    float bias = 0.f;
    if (is_j) {
        const u64* p = reinterpret_cast<const u64*>(W_ih + j * I_);
        #pragma unroll
        for (int q = 0; q < 25; q++) wih[q] = p[q];
        bias = b_ih[j] + b_hh[j];
    }

    auto stage = [&](int tile, int buf) {
        const float* src = x + (size_t)tile * (XP_ROWS * I_);
        for (int i = tid; i < XP_ROWS * 25; i += 256) {
            int row = i / 25, c = i - 25 * row;
            cp8(&xs[buf][row * XP_RPAD + 2 * c], src + row * I_ + 2 * c);
        }
    };

    int tile = blockIdx.x;
    if (tile < XP_NT) stage(tile, 0);
    CP_COMMIT();

    int pb = 0;
    for (; tile < XP_NT; tile += gridDim.x) {
        const int nxt = tile + gridDim.x;
        if (nxt < XP_NT) stage(nxt, pb ^ 1);
        CP_COMMIT();
        CP_WAIT(1);
        __syncthreads();

        if (is_j) {
            float* orow = g_xp + (size_t)tile * XP_ROWS * H_ + j;
            #pragma unroll 2
            for (int i = 0; i < XP_ROWS / 2; i++) {
                const int row = 2 * i + r2;
                const float* rbase = xs[pb] + row * XP_RPAD;
                const ulonglong2* av =
                    reinterpret_cast<const ulonglong2*>(rbase);
                u64 a0 = 0, a1 = 0, a2 = 0, a3 = 0;
                #pragma unroll
                for (int q = 0; q < 12; q++) {
                    ulonglong2 v = av[q];
                    if (q & 1) {
                        a2 = fma2(wih[2 * q],     v.x, a2);
                        a3 = fma2(wih[2 * q + 1], v.y, a3);
                    } else {
                        a0 = fma2(wih[2 * q],     v.x, a0);
                        a1 = fma2(wih[2 * q + 1], v.y, a1);
                    }
                }
                a0 = fma2(wih[24],
                          reinterpret_cast<const u64*>(rbase)[24], a0);
                orow[(size_t)row * H_] =
                    pair_sum(add2(add2(a0, a1), add2(a2, a3))) + bias;
            }
        }
        __syncthreads();
        pb ^= 1;
    }
}

// ================= recurrence (R8, measured 612us): ========================
// h(t+1) = relu(xp(t) + W_hh·h(t)). 256 CTAs x 128 threads, 1 row/CTA,
// 2 CTAs/SM. Thread j holds the FULL W_hh row j in registers; h(t) read via
// perfect-broadcast LDS.128; xp prefetched 2 steps ahead via __ldg.
__global__ void __launch_bounds__(128, 2) rnn_kernel(
    const float* __restrict__ W_hh)
{
    __shared__ __align__(16) float h_s[2][120];   // ping-pong, 116 used

    const int j = threadIdx.x;
    const int b = blockIdx.x;
    const bool comp = (j < H_);

    if (j < 120) { h_s[0][j] = 0.f; h_s[1][j] = 0.f; }

    u64 w[58];
    if (comp) {
        const u64* ws = reinterpret_cast<const u64*>(W_hh + j * H_);
        #pragma unroll
        for (int q = 0; q < 58; q++) w[q] = ws[q];
    }

    const float* xpb = g_xp + (size_t)b * T_ * H_ + j;
    float xpr0 = 0.f, xpr1 = 0.f;
    if (comp) { xpr0 = __ldg(xpb); xpr1 = __ldg(xpb + H_); }
    __syncthreads();

    float* hs_ptr = g_hs + (size_t)b * T_ * H_ + j;
    int p = 0;

#define RNN_STEP(XPR, TNEXT)                                                 \
    {                                                                        \
        u64 a0 = (u64)__float_as_uint(XPR);        /* consume xp(t) */       \
        if (comp && (TNEXT) < T_)                  /* refill, 2-step slack */\
            XPR = __ldg(xpb + (size_t)(TNEXT) * H_);                         \
        u64 a1 = 0, a2 = 0, a3 = 0;                                          \
        const ulonglong2* hv =                                               \
            reinterpret_cast<const ulonglong2*>(h_s[p]);                     \
        _Pragma("unroll")                                                    \
        for (int q = 0; q < 29; q++) {                                       \
            ulonglong2 v = hv[q];                                            \
            if (q & 1) { a2 = fma2(w[2 * q],     v.x, a2);                   \
                         a3 = fma2(w[2 * q + 1], v.y, a3); }                 \
            else       { a0 = fma2(w[2 * q],     v.x, a0);                   \
                         a1 = fma2(w[2 * q + 1], v.y, a1); }                 \
        }                                                                    \
        if (comp) {                                                          \
            float h = fmaxf(                                                 \
                pair_sum(add2(add2(a0, a1), add2(a2, a3))), 0.f);            \
            h_s[p ^ 1][j] = h;                                               \
            hs_ptr[0] = h; hs_ptr += H_;                                     \
        }                                                                    \
        __syncthreads();                                                     \
        p ^= 1;                                                              \
    }

    for (int t = 0; t < T_; t += 2) {
        RNN_STEP(xpr0, t + 2)
        RNN_STEP(xpr1, t + 3)
    }
#undef RNN_STEP
}

// ================= FC GEMM: out[n,o] = hs[n,:]·W_fc[o,:] + b_fc[o] =========
// 2-outputs-per-thread, quarter k-split. Lane l<100: oo=l>>2 in [0,25),
// qq=l&3. Thread holds W_fc quarters (32 floats, zero-padded past 116) of
// outputs oo AND oo+25 -> each 8x LDS.128 h-quarter feeds 32 fma2 (4:1).
// hs_s rows padded to 128 floats (pads zeroed once). Quarter chunks are read
// in qq-rotated order (i+2qq)&7 so the 4 qq-lanes hit disjoint bank groups;
// the rotation is baked into the WEIGHT LOAD ORDER so all register indices
// stay compile-time. Reduction: shfl_xor 1 then 2 across the 4 qq lanes.
#define FC_ROWS 32
#define FC_NT   (N_TOT / FC_ROWS)
__global__ void __launch_bounds__(256, 2) fc_kernel(
    const float* __restrict__ W_fc,
    const float* __restrict__ b_fc,
    float* __restrict__ out)
{
    __shared__ __align__(16) float hs_s[2][FC_ROWS][128];

    const int tid = threadIdx.x;
    const int l   = tid & 127;
    const int g   = tid >> 7;        // row parity group
    const int oo  = l >> 2;          // 0..31, active < 25
    const int qq  = l & 3;
    const bool act = (l < 100);

    // zero pad columns [116,128) of both buffers (staging never writes them)
    for (int i = tid; i < 2 * FC_ROWS * 12; i += 256) {
        int buf = i / (FC_ROWS * 12);
        int rr  = (i / 12) % FC_ROWS;
        int cc  = i % 12;
        hs_s[buf][rr][116 + cc] = 0.f;
    }

    // ---- weights: quarters of W_fc rows oo and oo+25, in rotated order ----
    u64 wa[16], wb[16];
    #pragma unroll
    for (int k = 0; k < 16; k++) { wa[k] = 0ull; wb[k] = 0ull; }
    float biasA = 0.f, biasB = 0.f;
    if (act) {
        const u64* wsA = reinterpret_cast<const u64*>(W_fc + oo * H_);
        const u64* wsB = reinterpret_cast<const u64*>(W_fc + (oo + 25) * H_);
        const int base = qq * 16;    // u64 index of my quarter start
        #pragma unroll
        for (int i = 0; i < 8; i++) {
            const int c = (i + 2 * qq) & 7;        // rotated chunk
            const int e0 = base + 2 * c;
            if (e0 < 58)     { wa[2 * i]     = wsA[e0];     wb[2 * i]     = wsB[e0]; }
            if (e0 + 1 < 58) { wa[2 * i + 1] = wsA[e0 + 1]; wb[2 * i + 1] = wsB[e0 + 1]; }
        }
        biasA = b_fc[oo];
        biasB = b_fc[oo + 25];
    }

    const float* hs = g_hs;
    auto stage = [&](int tile, int buf) {
        const float* src = hs + (size_t)tile * (FC_ROWS * H_);
        for (int i = tid; i < FC_ROWS * 29; i += 256) {
            int row = i / 29, c = i - 29 * row;
            cp16(&hs_s[buf][row][4 * c], src + (size_t)row * H_ + 4 * c);
        }
    };

    int tile = blockIdx.x;
    if (tile < FC_NT) stage(tile, 0);
    CP_COMMIT();

    int pb = 0;
    for (; tile < FC_NT; tile += gridDim.x) {
        const int nxt = tile + gridDim.x;
        if (nxt < FC_NT) stage(nxt, pb ^ 1);
        CP_COMMIT();
        CP_WAIT(1);
        __syncthreads();

        #pragma unroll 2
        for (int i = 0; i < FC_ROWS / 2; i++) {
            const int row = 2 * i + g;
            const ulonglong2* hv = reinterpret_cast<const ulonglong2*>(
                hs_s[pb][row]) + qq * 8;
            u64 a0 = 0, a1 = 0, b0 = 0, b1 = 0;
            #pragma unroll
            for (int k = 0; k < 8; k++) {
                ulonglong2 v = hv[(k + 2 * qq) & 7];   // rotated read
                a0 = fma2(wa[2 * k],     v.x, a0);
                a1 = fma2(wa[2 * k + 1], v.y, a1);
                b0 = fma2(wb[2 * k],     v.x, b0);
                b1 = fma2(wb[2 * k + 1], v.y, b1);
            }
            float pA = pair_sum(add2(a0, a1));
            float pB = pair_sum(add2(b0, b1));
            pA += __shfl_xor_sync(0xFFFFFFFFu, pA, 1);
            pB += __shfl_xor_sync(0xFFFFFFFFu, pB, 1);
            pA += __shfl_xor_sync(0xFFFFFFFFu, pA, 2);
            pB += __shfl_xor_sync(0xFFFFFFFFu, pB, 2);
            if (act && qq == 0) {
                float* orow = out + (size_t)(tile * FC_ROWS + row) * O_;
                orow[oo]      = pA + biasA;
                orow[oo + 25] = pB + biasB;
            }
        }
        __syncthreads();
        pb ^= 1;
    }
}

// Probe kernel: occupies the 3rd launch slot so the ncu capture (4th launch)
// lands on fc_kernel.
__global__ void probe_kernel() {
    if (threadIdx.x == 0 && blockIdx.x == 0) g_dummy = g_dummy;
}

// ---------------- launch ----------------
extern "C" void kernel_launch(void* const* d_in, const int* in_sizes, int n_in,
                              void* d_out, int out_size)
{
    const float* x    = (const float*)d_in[0];
    const float* W_ih = (const float*)d_in[1];
    const float* b_ih = (const float*)d_in[2];
    const float* W_hh = (const float*)d_in[3];
    const float* b_hh = (const float*)d_in[4];
    const float* W_fc = (const float*)d_in[5];
    const float* b_fc = (const float*)d_in[6];
    float* out = (float*)d_out;

    xp_kernel<<<4096, 256>>>(x, W_ih, b_ih, b_hh);
    rnn_kernel<<<B_, 128>>>(W_hh);
    probe_kernel<<<1, 32>>>();
    fc_kernel<<<2048, 256>>>(W_fc, b_fc, out);
}